// round 4
// baseline (speedup 1.0000x reference)
#include <cuda_runtime.h>
#include <cuda_bf16.h>
#include <cstdint>

#define BB 16
#define CIN 3
#define HH 256
#define WW 256
#define COUT 64
#define NPIX (BB*HH*WW)
#define PLANE (HH*WW)
#define KTOT 54
#define NBLK (BB*HH)              // 4096 row-blocks

typedef unsigned long long ull;

// BN partial sums: [channel][block]
__device__ float g_partS[COUT * NBLK];
__device__ float g_partQ[COUT * NBLK];
__device__ float g_scale[COUT];
__device__ float g_shift[COUT];

// ---- dynamic SMEM layout (bytes, 16B aligned) ----
#define OFF_W    0                        // float[54][64]       13824 (scalar weights)
#define OFF_BDUP (OFF_W + 54*64*4)        // ull[64]               512
#define OFF_TAPS (OFF_BDUP + 64*8)        // float[54][256]      55296 (overlaid by rs/rq in epilogue)
#define OFF_RS   OFF_TAPS                 // float[64][33]        8448
#define OFF_RQ   (OFF_RS + 64*33*4)       // float[64][33]        8448
#define OFF_X    (OFF_TAPS + 54*256*4)    // float[3][5][264]    15840  (5-row window)
#define OFF_WOFF (OFF_X + 3*5*264*4)      // float[18][32]        2304  (padded rows, 128B aligned)
#define SMEM_BYTES (OFF_WOFF + 18*32*4)   // = 87776

__device__ __forceinline__ void fma2(ull& a, ull b, ull c) {
    asm("fma.rn.f32x2 %0, %1, %2, %0;" : "+l"(a) : "l"(b), "l"(c));
}
__device__ __forceinline__ ull add2(ull a, ull b) {
    ull r; asm("add.rn.f32x2 %0, %1, %2;" : "=l"(r) : "l"(a), "l"(b)); return r;
}
__device__ __forceinline__ ull dup2(float w) {
    ull r; asm("mov.b64 %0, {%1, %1};" : "=l"(r) : "r"(__float_as_uint(w))); return r;
}
__device__ __forceinline__ ull pack2(float a, float b) {
    ull r; asm("mov.b64 %0, {%1, %2};" : "=l"(r) : "r"(__float_as_uint(a)), "r"(__float_as_uint(b))); return r;
}
__device__ __forceinline__ float lo32(ull v) { return __uint_as_float((unsigned)v); }
__device__ __forceinline__ float hi32(ull v) { return __uint_as_float((unsigned)(v >> 32)); }

// ---------------------------------------------------------------------------
// Kernel A: offset-conv (f32x2, vectorized weight loads) + SMEM bilinear
// sampling -> taps in SMEM -> register-blocked fused GEMM (8ch x 8px, f32x2)
// + fused BN partial reduction. One block = one (b,h) row of 256 pixels.
// ---------------------------------------------------------------------------
__global__ __launch_bounds__(256, 2)
void fused_main(const float* __restrict__ x,
                const float* __restrict__ w_off,
                const float* __restrict__ b_off,
                const float* __restrict__ w_dcn,
                const float* __restrict__ w_conv,
                const float* __restrict__ b_conv,
                float* __restrict__ out)
{
    extern __shared__ __align__(16) char smem[];
    float* s_w    = (float*)(smem + OFF_W);      // [k*64 + c]
    ull*   s_bdup = (ull*)  (smem + OFF_BDUP);
    float* s_taps = (float*)(smem + OFF_TAPS);   // [k*256 + p]
    float* s_rs   = (float*)(smem + OFF_RS);     // [c*33 + pg]
    float* s_rq   = (float*)(smem + OFF_RQ);
    float* s_x    = (float*)(smem + OFF_X);      // [(ci*5+r)*264 + col], rows h-2..h+2
    float* s_woff = (float*)(smem + OFF_WOFF);   // [o*32 + j]
    __shared__ float s_boff[18];

    const int tid  = threadIdx.x;
    const int bidx = blockIdx.x;
    const int b    = bidx >> 8;
    const int h    = bidx & 255;

    // ---- stage weights (scalar) ----
    for (int i = tid; i < KTOT*COUT; i += 256) {
        int k = i >> 6, c = i & 63;
        s_w[i] = (k < 27) ? w_conv[c*27 + k] : w_dcn[c*27 + (k - 27)];
    }
    for (int i = tid; i < 18*32; i += 256) {
        int o = i >> 5, j = i & 31;
        s_woff[i] = (j < 27) ? w_off[o*27 + j] : 0.f;
    }
    if (tid < COUT) {
        float bv = b_conv[tid];
        s_bdup[tid] = (ull)__float_as_uint(bv) | ((ull)__float_as_uint(bv) << 32);
    }
    if (tid < 18) s_boff[tid] = b_off[tid];

    // ---- stage x rows h-2..h+2 with 1-col halo ----
    for (int i = tid; i < 3*5*258; i += 256) {
        int ci = i / (5*258);
        int r  = (i / 258) % 5;
        int cc = i % 258;
        int gy = h - 2 + r;
        int gx = cc - 1;
        float v = 0.f;
        if (gy >= 0 && gy < HH && gx >= 0 && gx < WW)
            v = x[((size_t)(b*3 + ci)*HH + gy)*WW + gx];
        s_x[(ci*5 + r)*264 + cc] = v;
    }
    __syncthreads();

    // ================= Phase 1: build taps for pixel w = tid =================
    {
        const int w = tid;

        // im2col taps (rows 1..3 of the 5-row window are h-1..h+1)
        float fv[27];
        #pragma unroll
        for (int ci = 0; ci < 3; ci++)
            #pragma unroll
            for (int k = 0; k < 9; k++)
                fv[ci*9 + k] = s_x[(ci*5 + 1 + k/3)*264 + w + (k%3)];

        // write im2col taps now
        #pragma unroll
        for (int k = 0; k < 27; k++)
            s_taps[(k << 8) + w] = fv[k];

        // pack taps into f32x2 pairs (pad to 28)
        ull fvp[14];
        #pragma unroll
        for (int q = 0; q < 13; q++) fvp[q] = pack2(fv[2*q], fv[2*q+1]);
        fvp[13] = pack2(fv[26], 0.f);

        // per-tap: offset conv (vectorized) then bilinear sample from SMEM
        #pragma unroll
        for (int k = 0; k < 9; k++) {
            ull ay = 0ULL, ax = 0ULL;
            const ulonglong2* wy = reinterpret_cast<const ulonglong2*>(s_woff + (2*k)*32);
            const ulonglong2* wx = reinterpret_cast<const ulonglong2*>(s_woff + (2*k+1)*32);
            #pragma unroll
            for (int q = 0; q < 7; q++) {
                ulonglong2 py2 = wy[q];
                ulonglong2 px2 = wx[q];
                fma2(ay, py2.x, fvp[2*q]);
                fma2(ax, px2.x, fvp[2*q]);
                if (q < 6) {   // pair index 2q+1 valid for q<7 -> 13 pairs used + pad
                    fma2(ay, py2.y, fvp[2*q+1]);
                    fma2(ax, px2.y, fvp[2*q+1]);
                }
            }
            // include the last pair (index 13) from vec q=6 .y
            {
                ulonglong2 py2 = wy[6];
                ulonglong2 px2 = wx[6];
                fma2(ay, py2.y, fvp[13]);
                fma2(ax, px2.y, fvp[13]);
            }
            float dy = lo32(ay) + hi32(ay) + s_boff[2*k];
            float dx = lo32(ax) + hi32(ax) + s_boff[2*k+1];

            float py = (float)(h + k/3 - 1) + dy;
            float px = (float)(w + k%3 - 1) + dx;
            float y0 = floorf(py), x0 = floorf(px);
            float ly = py - y0,    lx = px - x0;
            float hy = 1.f - ly,   hx = 1.f - lx;
            float y1 = y0 + 1.f,   x1 = x0 + 1.f;
            bool vy0 = (y0 >= 0.f) && (y0 <= 255.f);
            bool vy1 = (y1 >= 0.f) && (y1 <= 255.f);
            bool vx0 = (x0 >= 0.f) && (x0 <= 255.f);
            bool vx1 = (x1 >= 0.f) && (x1 <= 255.f);
            float w00 = hy*hx * ((vy0 && vx0) ? 1.f : 0.f);
            float w01 = hy*lx * ((vy0 && vx1) ? 1.f : 0.f);
            float w10 = ly*hx * ((vy1 && vx0) ? 1.f : 0.f);
            float w11 = ly*lx * ((vy1 && vx1) ? 1.f : 0.f);
            int iy0 = min(max((int)y0, 0), 255);
            int iy1 = min(max((int)y1, 0), 255);
            int ix0 = min(max((int)x0, 0), 255);
            int ix1 = min(max((int)x1, 0), 255);
            // local window rows (h-2..h+2); valid corners always inside,
            // invalid ones are clamped (their weight is 0)
            int ly0 = min(max(iy0 - (h - 2), 0), 4);
            int ly1 = min(max(iy1 - (h - 2), 0), 4);
            int lx0 = ix0 + 1;
            int lx1 = ix1 + 1;
            int i00 = ly0*264 + lx0, i01 = ly0*264 + lx1;
            int i10 = ly1*264 + lx0, i11 = ly1*264 + lx1;
            #pragma unroll
            for (int ci = 0; ci < 3; ci++) {
                const float* xc = s_x + ci*1320;   // 5*264
                float v = w00 * xc[i00] + w01 * xc[i01]
                        + w10 * xc[i10] + w11 * xc[i11];
                s_taps[((27 + ci*9 + k) << 8) + w] = v;
            }
        }
    }
    __syncthreads();

    // ========== Phase 2: 8 channels x 8 pixels per thread, f32x2 ==========
    const int cg    = tid & 7;      // channel group: channels 8cg..8cg+7
    const int pg    = tid >> 3;     // pixel group:   pixels 8pg..8pg+7
    const int pbase = pg << 3;
    const int cbase = cg << 3;

    ull acc[8][4];
    #pragma unroll
    for (int c = 0; c < 8; c++)
        #pragma unroll
        for (int p = 0; p < 4; p++) acc[c][p] = 0ULL;

    #pragma unroll 2
    for (int k = 0; k < KTOT; k++) {
        const float4* wr = reinterpret_cast<const float4*>(s_w + (k << 6) + cbase);
        float4 w0 = wr[0], w1 = wr[1];
        const ulonglong2* tp = reinterpret_cast<const ulonglong2*>(s_taps + (k << 8) + pbase);
        ulonglong2 tA = tp[0], tB = tp[1];
        ull tv[4] = {tA.x, tA.y, tB.x, tB.y};
        float wv[8] = {w0.x, w0.y, w0.z, w0.w, w1.x, w1.y, w1.z, w1.w};
        #pragma unroll
        for (int c = 0; c < 8; c++) {
            ull wd = dup2(wv[c]);
            #pragma unroll
            for (int p = 0; p < 4; p++)
                fma2(acc[c][p], wd, tv[p]);
        }
    }
    __syncthreads();   // protect s_taps before rs/rq overlay

    // ---- epilogue: bias, store, BN partials ----
    float* outrow = out + (size_t)b * COUT * PLANE + (size_t)h * WW + pbase;
    #pragma unroll
    for (int c = 0; c < 8; c++) {
        const int C = cbase + c;
        const ull bias2 = s_bdup[C];
        ull v[4];
        #pragma unroll
        for (int p = 0; p < 4; p++) v[p] = add2(acc[c][p], bias2);

        ulonglong2* op = reinterpret_cast<ulonglong2*>(outrow + ((size_t)C << 16));
        op[0] = make_ulonglong2(v[0], v[1]);
        op[1] = make_ulonglong2(v[2], v[3]);

        ull S = add2(add2(v[0], v[1]), add2(v[2], v[3]));
        ull Q = 0ULL;
        #pragma unroll
        for (int p = 0; p < 4; p++) fma2(Q, v[p], v[p]);
        s_rs[C*33 + pg] = lo32(S) + hi32(S);
        s_rq[C*33 + pg] = lo32(Q) + hi32(Q);
    }
    __syncthreads();

    if (tid < COUT) {
        float s = 0.f, q = 0.f;
        #pragma unroll
        for (int p = 0; p < 32; p++) { s += s_rs[tid*33 + p]; q += s_rq[tid*33 + p]; }
        g_partS[tid*NBLK + bidx] = s;
        g_partQ[tid*NBLK + bidx] = q;
    }
}

// ---------------------------------------------------------------------------
// Kernel B: per-channel stats finalize (one block per channel)
// ---------------------------------------------------------------------------
__global__ __launch_bounds__(256)
void stats_kernel(const float* __restrict__ gamma,
                  const float* __restrict__ beta)
{
    const int c = blockIdx.x;
    const int tid = threadIdx.x;
    float s = 0.f, q = 0.f;
    for (int i = tid; i < NBLK; i += 256) {
        s += g_partS[c*NBLK + i];
        q += g_partQ[c*NBLK + i];
    }
    __shared__ float ss[256], sq[256];
    ss[tid] = s; sq[tid] = q;
    __syncthreads();
    for (int st = 128; st > 0; st >>= 1) {
        if (tid < st) { ss[tid] += ss[tid+st]; sq[tid] += sq[tid+st]; }
        __syncthreads();
    }
    if (tid == 0) {
        const float invN = 1.f / (float)NPIX;
        float mean = ss[0] * invN;
        float var  = sq[0] * invN - mean * mean;
        float inv  = rsqrtf(var + 1e-5f);
        float sc   = gamma[c] * inv;
        g_scale[c] = sc;
        g_shift[c] = beta[c] - mean * sc;
    }
}

// ---------------------------------------------------------------------------
// Kernel C: in-place normalize + SiLU (2 float4 per thread)
// ---------------------------------------------------------------------------
#define N4TOT ((size_t)BB*COUT*PLANE/4)   // 16777216
#define N4HALF (N4TOT/2)                  // 8388608

__global__ __launch_bounds__(256)
void norm_silu(float* __restrict__ y)
{
    const size_t i0 = (size_t)blockIdx.x * 256 + threadIdx.x;
    float4* yp = reinterpret_cast<float4*>(y);

    #pragma unroll
    for (int r = 0; r < 2; r++) {
        size_t idx = i0 + (size_t)r * N4HALF;
        int c = (int)((idx >> 14) & 63);
        float sc = g_scale[c];
        float sh = g_shift[c];
        float4 v = yp[idx];
        float t0 = fmaf(v.x, sc, sh);
        float t1 = fmaf(v.y, sc, sh);
        float t2 = fmaf(v.z, sc, sh);
        float t3 = fmaf(v.w, sc, sh);
        v.x = t0 / (1.f + __expf(-t0));
        v.y = t1 / (1.f + __expf(-t1));
        v.z = t2 / (1.f + __expf(-t2));
        v.w = t3 / (1.f + __expf(-t3));
        yp[idx] = v;
    }
}

// ---------------------------------------------------------------------------
extern "C" void kernel_launch(void* const* d_in, const int* in_sizes, int n_in,
                              void* d_out, int out_size)
{
    const float* x      = (const float*)d_in[0];
    const float* w_off  = (const float*)d_in[1];
    const float* b_off  = (const float*)d_in[2];
    const float* w_dcn  = (const float*)d_in[3];
    const float* w_conv = (const float*)d_in[4];
    const float* b_conv = (const float*)d_in[5];
    const float* gamma  = (const float*)d_in[6];
    const float* beta   = (const float*)d_in[7];
    float* out = (float*)d_out;

    cudaFuncSetAttribute(fused_main, cudaFuncAttributeMaxDynamicSharedMemorySize, SMEM_BYTES);

    fused_main<<<NBLK, 256, SMEM_BYTES>>>(x, w_off, b_off, w_dcn, w_conv, b_conv, out);
    stats_kernel<<<COUT, 256>>>(gamma, beta);
    norm_silu<<<N4HALF/256, 256>>>(out);
}